// round 1
// baseline (speedup 1.0000x reference)
#include <cuda_runtime.h>
#include <cstdint>

// ---------------- problem constants ----------------
#define CH     256
#define G      4
#define GC     64          // channels per group (in and out)
#define HYP    128
#define HD     2324
#define NW     36864       // 64*64*9
#define NB     64
#define NWB    36928       // NW+NB
#define BATCH  8
#define HW     4096        // 64*64

// ---------------- scratch (__device__ globals: no allocs allowed) ----------------
__device__ float g_h[G * BATCH * HD];            // hidden activations
__device__ float g_wT[G * BATCH * NW];           // weights transposed to [k][oc]
__device__ float g_bias[G * BATCH * NB];         // per-(g,b) output-channel bias

// ================= kernel 1: h = relu(hyper @ W1 + b1) =================
// grid (ceil(HD/256), G), block 256
__global__ void k_mlp1(const float* __restrict__ hyper,
                       const float* __restrict__ W1,
                       const float* __restrict__ b1)
{
    __shared__ float hy[BATCH * HYP];
    int tid = threadIdx.x;
    for (int i = tid; i < BATCH * HYP; i += 256) hy[i] = hyper[i];
    __syncthreads();

    int g = blockIdx.y;
    int d = blockIdx.x * 256 + tid;
    if (d >= HD) return;

    float acc[BATCH];
    #pragma unroll
    for (int b = 0; b < BATCH; ++b) acc[b] = 0.f;

    const float* w = W1 + (size_t)g * HYP * HD + d;
    #pragma unroll 4
    for (int i = 0; i < HYP; ++i) {
        float wv = w[(size_t)i * HD];
        #pragma unroll
        for (int b = 0; b < BATCH; ++b) acc[b] += hy[b * HYP + i] * wv;
    }
    float bv = b1[g * HD + d];
    #pragma unroll
    for (int b = 0; b < BATCH; ++b)
        g_h[((size_t)(g * BATCH + b)) * HD + d] = fmaxf(acc[b] + bv, 0.f);
}

// ================= kernel 2: gened = h @ W2 + b2, scatter to wT/bias ==========
// grid (37, G), block 256. Each thread owns 4 consecutive outputs (float4 row
// loads of W2) x 8 batches. One wave of 148 blocks; W2 (1.37 GB) streamed once.
__global__ void __launch_bounds__(256) k_mlp2(const float* __restrict__ W2,
                                              const float* __restrict__ b2)
{
    int g  = blockIdx.y;
    int o0 = blockIdx.x * 1024 + threadIdx.x * 4;
    bool active = (o0 < NWB);

    __shared__ float hs[32][8];

    float acc[BATCH][4];
    #pragma unroll
    for (int b = 0; b < BATCH; ++b)
        #pragma unroll
        for (int j = 0; j < 4; ++j) acc[b][j] = 0.f;

    const float* W2g = W2 + (size_t)g * HD * NWB;

    for (int d0 = 0; d0 < HD; d0 += 32) {
        // stage 32 x 8 h values
        {
            int dd = threadIdx.x >> 3, b = threadIdx.x & 7;
            int d  = d0 + dd;
            hs[dd][b] = (d < HD) ? g_h[((size_t)(g * BATCH + b)) * HD + d] : 0.f;
        }
        __syncthreads();
        if (active) {
            int dmax = min(32, HD - d0);
            #pragma unroll 4
            for (int dd = 0; dd < dmax; ++dd) {
                float4 wv = *(const float4*)(W2g + ((size_t)(d0 + dd)) * NWB + o0);
                #pragma unroll
                for (int b = 0; b < BATCH; ++b) {
                    float hv = hs[dd][b];
                    acc[b][0] = fmaf(hv, wv.x, acc[b][0]);
                    acc[b][1] = fmaf(hv, wv.y, acc[b][1]);
                    acc[b][2] = fmaf(hv, wv.z, acc[b][2]);
                    acc[b][3] = fmaf(hv, wv.w, acc[b][3]);
                }
            }
        }
        __syncthreads();
    }

    if (!active) return;

    float bb[4];
    #pragma unroll
    for (int j = 0; j < 4; ++j) bb[j] = b2[(size_t)g * NWB + o0 + j];

    #pragma unroll
    for (int b = 0; b < BATCH; ++b) {
        size_t gb = (size_t)(g * BATCH + b);
        #pragma unroll
        for (int j = 0; j < 4; ++j) {
            int o = o0 + j;
            float v = acc[b][j] + bb[j];
            if (o < NW) {
                int oc = o / 576;       // output channel
                int k  = o % 576;       // c_local*9 + tap
                g_wT[gb * NW + (size_t)k * GC + oc] = v;
            } else {
                g_bias[gb * NB + (o - NW)] = v;
            }
        }
    }
}

// ================= kernel 3: grouped dynamic 3x3 conv + bias =================
// grid (16 tiles, G, BATCH), block 256. 16x16 pixel tile, 64 oc.
// Per input channel: SMEM 18x18 halo tile + 576 weights ([tap][oc], coalesced
// from g_wT). Thread register-blocks 8 oc x 8 px.
__global__ void __launch_bounds__(256) k_conv(const float* __restrict__ image,
                                              float* __restrict__ out)
{
    int b = blockIdx.z, g = blockIdx.y;
    int tile = blockIdx.x;
    int tr = (tile >> 2) * 16, tc = (tile & 3) * 16;

    __shared__ float xs[18 * 18];
    __shared__ float ws[576];

    int tid = threadIdx.x;
    int oc0 = (tid & 7) * 8;            // 8 output channels
    int pxg = tid >> 3;                 // 0..31
    int pr  = pxg >> 1;                 // row 0..15 in tile
    int pc0 = (pxg & 1) * 8;            // col 0 or 8

    float acc[8][8];
    #pragma unroll
    for (int a = 0; a < 8; ++a)
        #pragma unroll
        for (int p = 0; p < 8; ++p) acc[a][p] = 0.f;

    const float* wT  = g_wT + (size_t)(g * BATCH + b) * NW;
    const float* img = image + (((size_t)b * CH + g * GC)) * HW;

    for (int c = 0; c < GC; ++c) {
        __syncthreads();
        // image halo tile
        const float* ic = img + (size_t)c * HW;
        for (int i = tid; i < 324; i += 256) {
            int r = i / 18, cc = i - r * 18;
            int gr = tr - 1 + r, gcx = tc - 1 + cc;
            xs[i] = (gr >= 0 && gr < 64 && gcx >= 0 && gcx < 64)
                    ? ic[gr * 64 + gcx] : 0.f;
        }
        // weights for this input channel: contiguous 576 floats [tap][oc]
        const float* wsl = wT + (size_t)c * 9 * GC;
        for (int i = tid; i < 576; i += 256) ws[i] = wsl[i];
        __syncthreads();

        float xr[3][10];
        #pragma unroll
        for (int kh = 0; kh < 3; ++kh)
            #pragma unroll
            for (int j = 0; j < 10; ++j)
                xr[kh][j] = xs[(pr + kh) * 18 + pc0 + j];

        #pragma unroll
        for (int kh = 0; kh < 3; ++kh) {
            #pragma unroll
            for (int kw = 0; kw < 3; ++kw) {
                float wv[8];
                #pragma unroll
                for (int a = 0; a < 8; ++a)
                    wv[a] = ws[(kh * 3 + kw) * GC + oc0 + a];
                #pragma unroll
                for (int a = 0; a < 8; ++a)
                    #pragma unroll
                    for (int p = 0; p < 8; ++p)
                        acc[a][p] = fmaf(wv[a], xr[kh][p + kw], acc[a][p]);
            }
        }
    }

    // epilogue: add bias, write out
    #pragma unroll
    for (int a = 0; a < 8; ++a) {
        float bv = g_bias[(size_t)(g * BATCH + b) * NB + oc0 + a];
        float* op = out + (((size_t)b * CH + g * GC + oc0 + a)) * HW
                        + (tr + pr) * 64 + tc + pc0;
        #pragma unroll
        for (int p = 0; p < 8; ++p) op[p] = acc[a][p] + bv;
    }
}

// ================= launch =================
extern "C" void kernel_launch(void* const* d_in, const int* in_sizes, int n_in,
                              void* d_out, int out_size)
{
    const float* image = (const float*)d_in[0];
    const float* hyper = (const float*)d_in[1];
    const float* W1    = (const float*)d_in[2];
    const float* b1    = (const float*)d_in[3];
    const float* W2    = (const float*)d_in[4];
    const float* b2    = (const float*)d_in[5];
    float*       out   = (float*)d_out;

    dim3 g1((HD + 255) / 256, G);
    k_mlp1<<<g1, 256>>>(hyper, W1, b1);

    dim3 g2((NWB + 1023) / 1024, G);    // 37 x 4 = 148 blocks, one wave
    k_mlp2<<<g2, 256>>>(W2, b2);

    dim3 g3(16, G, BATCH);
    k_conv<<<g3, 256>>>(image, out);
}

// round 3
// speedup vs baseline: 2.2074x; 2.2074x over previous
#include <cuda_runtime.h>
#include <cstdint>

// ---------------- problem constants ----------------
#define CH     256
#define G      4
#define GC     64          // channels per group (in and out)
#define HYP    128
#define HD     2324
#define NW     36864       // 64*64*9
#define NB     64
#define NWB    36928       // NW+NB
#define BATCH  8
#define HW     4096        // 64*64

typedef unsigned long long u64;

// ---------------- scratch (__device__ globals: no allocs allowed) ----------------
__device__ float g_h[G * BATCH * HD];            // hidden activations
__device__ float g_wT[G * BATCH * NW];           // weights transposed to [c][tap][oc]
__device__ float g_bias[G * BATCH * NB];         // per-(g,b) output-channel bias

// ---------------- f32x2 packed helpers ----------------
__device__ __forceinline__ u64 pack2(float lo, float hi) {
    u64 r;
    asm("mov.b64 %0,{%1,%2};" : "=l"(r)
        : "r"(__float_as_uint(lo)), "r"(__float_as_uint(hi)));
    return r;
}
__device__ __forceinline__ void fma2(u64& d, u64 a, u64 b) {
    asm("fma.rn.f32x2 %0, %1, %2, %0;" : "+l"(d) : "l"(a), "l"(b));
}
__device__ __forceinline__ float2 unpack2(u64 v) {
    unsigned lo, hi;
    asm("mov.b64 {%0,%1},%2;" : "=r"(lo), "=r"(hi) : "l"(v));
    return make_float2(__uint_as_float(lo), __uint_as_float(hi));
}

// ---------------- cp.async helpers ----------------
__device__ __forceinline__ unsigned scvt(const void* p) {
    return (unsigned)__cvta_generic_to_shared(p);
}
// 4-byte cp.async; if pred==false, src-size=0 => zero-fill destination.
__device__ __forceinline__ void cpa4(unsigned d, const float* s, bool pred) {
    int sz = pred ? 4 : 0;
    asm volatile("cp.async.ca.shared.global [%0],[%1],4,%2;\n"
                 :: "r"(d), "l"(s), "r"(sz));
}
__device__ __forceinline__ void cpa16(unsigned d, const float* s) {
    asm volatile("cp.async.cg.shared.global [%0],[%1],16;\n" :: "r"(d), "l"(s));
}
__device__ __forceinline__ void cp_commit() {
    asm volatile("cp.async.commit_group;\n" ::);
}
__device__ __forceinline__ void cp_wait_all() {
    asm volatile("cp.async.wait_group 0;\n" ::);
}

// ================= kernel 1: h = relu(hyper @ W1 + b1) =================
__global__ void k_mlp1(const float* __restrict__ hyper,
                       const float* __restrict__ W1,
                       const float* __restrict__ b1)
{
    __shared__ float hy[BATCH * HYP];
    int tid = threadIdx.x;
    for (int i = tid; i < BATCH * HYP; i += 256) hy[i] = hyper[i];
    __syncthreads();

    int g = blockIdx.y;
    int d = blockIdx.x * 256 + tid;
    if (d >= HD) return;

    float acc[BATCH];
    #pragma unroll
    for (int b = 0; b < BATCH; ++b) acc[b] = 0.f;

    const float* w = W1 + (size_t)g * HYP * HD + d;
    #pragma unroll 16
    for (int i = 0; i < HYP; ++i) {
        float wv = w[(size_t)i * HD];
        #pragma unroll
        for (int b = 0; b < BATCH; ++b) acc[b] += hy[b * HYP + i] * wv;
    }
    float bv = b1[g * HD + d];
    #pragma unroll
    for (int b = 0; b < BATCH; ++b)
        g_h[((size_t)(g * BATCH + b)) * HD + d] = fmaxf(acc[b] + bv, 0.f);
}

// ================= kernel 2: gened = h @ W2 + b2, scatter to wT/bias ==========
// grid (37, G) = 148 blocks (one wave), block 256. Thread owns 4 outputs x 8
// batches (batch-pairs packed for f32x2). 8 float4 LDGs batched per chunk to
// keep ~32KB in flight per SM -> stream W2 (1.37 GB) at the HBM floor.
__global__ void __launch_bounds__(256, 1) k_mlp2(const float* __restrict__ W2,
                                                 const float* __restrict__ b2)
{
    int g  = blockIdx.y;
    int o0 = blockIdx.x * 1024 + threadIdx.x * 4;
    bool active = (o0 < NWB);

    __shared__ __align__(16) float hs[32][8];

    u64 acc2[4][4];                 // [batch-pair][j]
    #pragma unroll
    for (int bp = 0; bp < 4; ++bp)
        #pragma unroll
        for (int j = 0; j < 4; ++j) acc2[bp][j] = 0ull;

    const float* W2g = W2 + (size_t)g * HD * NWB;
    int sdd = threadIdx.x >> 3, sb = threadIdx.x & 7;

    // main loop: 72 full 32-chunks (d in [0, 2304))
    for (int d0 = 0; d0 < 2304; d0 += 32) {
        hs[sdd][sb] = g_h[((size_t)(g * BATCH + sb)) * HD + d0 + sdd];
        __syncthreads();
        if (active) {
            #pragma unroll
            for (int du = 0; du < 32; du += 8) {
                float4 w[8];
                #pragma unroll
                for (int j = 0; j < 8; ++j)
                    w[j] = *(const float4*)(W2g + (size_t)(d0 + du + j) * NWB + o0);
                #pragma unroll
                for (int j = 0; j < 8; ++j) {
                    u64 wp[4];
                    wp[0] = pack2(w[j].x, w[j].x);
                    wp[1] = pack2(w[j].y, w[j].y);
                    wp[2] = pack2(w[j].z, w[j].z);
                    wp[3] = pack2(w[j].w, w[j].w);
                    const u64* hrow = (const u64*)&hs[du + j][0];
                    #pragma unroll
                    for (int bp = 0; bp < 4; ++bp) {
                        u64 hp = hrow[bp];
                        fma2(acc2[bp][0], hp, wp[0]);
                        fma2(acc2[bp][1], hp, wp[1]);
                        fma2(acc2[bp][2], hp, wp[2]);
                        fma2(acc2[bp][3], hp, wp[3]);
                    }
                }
            }
        }
        __syncthreads();
    }
    // tail: d in [2304, 2324)
    {
        hs[sdd][sb] = (2304 + sdd < HD)
                      ? g_h[((size_t)(g * BATCH + sb)) * HD + 2304 + sdd] : 0.f;
        __syncthreads();
        if (active) {
            for (int dd = 0; dd < 20; ++dd) {
                float4 wv = *(const float4*)(W2g + (size_t)(2304 + dd) * NWB + o0);
                u64 wp[4];
                wp[0] = pack2(wv.x, wv.x);
                wp[1] = pack2(wv.y, wv.y);
                wp[2] = pack2(wv.z, wv.z);
                wp[3] = pack2(wv.w, wv.w);
                const u64* hrow = (const u64*)&hs[dd][0];
                #pragma unroll
                for (int bp = 0; bp < 4; ++bp) {
                    u64 hp = hrow[bp];
                    #pragma unroll
                    for (int j = 0; j < 4; ++j) fma2(acc2[bp][j], hp, wp[j]);
                }
            }
        }
    }

    if (!active) return;

    float bb[4];
    #pragma unroll
    for (int j = 0; j < 4; ++j) bb[j] = b2[(size_t)g * NWB + o0 + j];

    #pragma unroll
    for (int bp = 0; bp < 4; ++bp) {
        #pragma unroll
        for (int j = 0; j < 4; ++j) {
            float2 v = unpack2(acc2[bp][j]);
            int o = o0 + j;
            float v0 = v.x + bb[j], v1 = v.y + bb[j];
            size_t gb0 = (size_t)(g * BATCH + 2 * bp);
            size_t gb1 = gb0 + 1;
            if (o < NW) {
                int oc = o / 576;
                int k  = o % 576;          // c*9 + tap
                g_wT[gb0 * NW + (size_t)k * GC + oc] = v0;
                g_wT[gb1 * NW + (size_t)k * GC + oc] = v1;
            } else {
                g_bias[gb0 * NB + (o - NW)] = v0;
                g_bias[gb1 * NB + (o - NW)] = v1;
            }
        }
    }
}

// ================= kernel 3: grouped dynamic 3x3 conv + bias =================
// grid (16 tiles, G, BATCH), block 256. 16x16 pixel tile, 64 oc.
// Double-buffered cp.async staging (halo tile + weights) overlapped with
// compute; f32x2 packed FMAs over output-channel pairs.
__global__ void __launch_bounds__(256, 1) k_conv(const float* __restrict__ image,
                                                 float* __restrict__ out)
{
    int b = blockIdx.z, g = blockIdx.y;
    int tile = blockIdx.x;
    int tr = (tile >> 2) * 16, tc = (tile & 3) * 16;

    __shared__ __align__(16) float xs[2][324];
    __shared__ __align__(16) float ws[2][576];

    int tid = threadIdx.x;
    int oc0 = (tid & 7) * 8;            // 8 output channels (4 pairs)
    int pxg = tid >> 3;                 // 0..31
    int pr  = pxg >> 1;                 // row 0..15 in tile
    int pc0 = (pxg & 1) * 8;            // col 0 or 8

    u64 acc2[4][8];                     // [oc-pair][px]
    #pragma unroll
    for (int a = 0; a < 4; ++a)
        #pragma unroll
        for (int p = 0; p < 8; ++p) acc2[a][p] = 0ull;

    const float* wT  = g_wT + (size_t)(g * BATCH + b) * NW;
    const float* img = image + ((size_t)b * CH + g * GC) * HW;

    // stage channel c into buffer buf (324 halo pixels + 576 weights)
    auto stage = [&](int c, int buf) {
        const float* ic = img + (size_t)c * HW;
        // two strided passes: i = tid, tid+256 (324 total)
        for (int i = tid; i < 324; i += 256) {
            int r = i / 18, cc = i - r * 18;
            int gr = tr - 1 + r, gcx = tc - 1 + cc;
            bool ok = (gr >= 0 && gr < 64 && gcx >= 0 && gcx < 64);
            const float* src = ok ? (ic + gr * 64 + gcx) : ic;
            cpa4(scvt(&xs[buf][i]), src, ok);
        }
        const float* wsl = wT + (size_t)c * 576;
        if (tid < 144)
            cpa16(scvt(&ws[buf][tid * 4]), wsl + tid * 4);
    };

    stage(0, 0);
    cp_commit();

    for (int c = 0; c < GC; ++c) {
        int cur = c & 1;
        cp_wait_all();
        __syncthreads();                 // buf 'cur' ready; all prior compute done
        if (c + 1 < GC) { stage(c + 1, cur ^ 1); cp_commit(); }

        const float* xsb = xs[cur];
        const float* wsb = ws[cur];

        #pragma unroll
        for (int kh = 0; kh < 3; ++kh) {
            float xr[10];
            #pragma unroll
            for (int j = 0; j < 10; ++j)
                xr[j] = xsb[(pr + kh) * 18 + pc0 + j];
            u64 xb[10];
            #pragma unroll
            for (int j = 0; j < 10; ++j) xb[j] = pack2(xr[j], xr[j]);

            #pragma unroll
            for (int kw = 0; kw < 3; ++kw) {
                const u64* wrow = (const u64*)&wsb[(kh * 3 + kw) * GC + oc0];
                u64 wpk[4];
                #pragma unroll
                for (int a = 0; a < 4; ++a) wpk[a] = wrow[a];
                #pragma unroll
                for (int a = 0; a < 4; ++a)
                    #pragma unroll
                    for (int p = 0; p < 8; ++p)
                        fma2(acc2[a][p], wpk[a], xb[p + kw]);
            }
        }
        __syncthreads();                 // compute done before buf overwrite
    }

    // epilogue: add bias, write out
    const float* bias = g_bias + (size_t)(g * BATCH + b) * NB;
    #pragma unroll
    for (int a = 0; a < 4; ++a) {
        float bv0 = bias[oc0 + 2 * a];
        float bv1 = bias[oc0 + 2 * a + 1];
        float* op0 = out + ((size_t)b * CH + g * GC + oc0 + 2 * a) * HW
                         + (tr + pr) * 64 + tc + pc0;
        float* op1 = op0 + HW;
        #pragma unroll
        for (int p = 0; p < 8; ++p) {
            float2 v = unpack2(acc2[a][p]);
            op0[p] = v.x + bv0;
            op1[p] = v.y + bv1;
        }
    }
}

// ================= launch =================
extern "C" void kernel_launch(void* const* d_in, const int* in_sizes, int n_in,
                              void* d_out, int out_size)
{
    const float* image = (const float*)d_in[0];
    const float* hyper = (const float*)d_in[1];
    const float* W1    = (const float*)d_in[2];
    const float* b1    = (const float*)d_in[3];
    const float* W2    = (const float*)d_in[4];
    const float* b2    = (const float*)d_in[5];
    float*       out   = (float*)d_out;

    dim3 g1((HD + 255) / 256, G);
    k_mlp1<<<g1, 256>>>(hyper, W1, b1);

    dim3 g2((NWB + 1023) / 1024, G);    // 37 x 4 = 148 blocks, one wave
    k_mlp2<<<g2, 256>>>(W2, b2);

    dim3 g3(16, G, BATCH);
    k_conv<<<g3, 256>>>(image, out);
}

// round 4
// speedup vs baseline: 2.9466x; 1.3348x over previous
#include <cuda_runtime.h>
#include <cstdint>

// ---------------- problem constants ----------------
#define CH     256
#define G      4
#define GC     64          // channels per group (in and out)
#define HYP    128
#define HD     2324
#define NW     36864       // 64*64*9
#define NB     64
#define NWB    36928       // NW+NB
#define BATCH  8
#define HW     4096        // 64*64

typedef unsigned long long u64;

// ---------------- scratch (__device__ globals: no allocs allowed) ----------------
__device__ float g_h[G * BATCH * HD];            // hidden activations
__device__ float g_wA[G * BATCH * NW];           // weights row-major [oc][k], tf32-rounded
__device__ float g_bias[G * BATCH * NB];         // per-(g,b) output-channel bias

// ---------------- f32x2 packed helpers ----------------
__device__ __forceinline__ u64 pack2(float lo, float hi) {
    u64 r;
    asm("mov.b64 %0,{%1,%2};" : "=l"(r)
        : "r"(__float_as_uint(lo)), "r"(__float_as_uint(hi)));
    return r;
}
__device__ __forceinline__ void fma2(u64& d, u64 a, u64 b) {
    asm("fma.rn.f32x2 %0, %1, %2, %0;" : "+l"(d) : "l"(a), "l"(b));
}
__device__ __forceinline__ float2 unpack2(u64 v) {
    unsigned lo, hi;
    asm("mov.b64 {%0,%1},%2;" : "=r"(lo), "=r"(hi) : "l"(v));
    return make_float2(__uint_as_float(lo), __uint_as_float(hi));
}
__device__ __forceinline__ float to_tf32(float x) {
    unsigned r;
    asm("cvt.rna.tf32.f32 %0, %1;" : "=r"(r) : "f"(x));
    return __uint_as_float(r);
}

// ---------------- cp.async helpers ----------------
__device__ __forceinline__ unsigned scvt(const void* p) {
    return (unsigned)__cvta_generic_to_shared(p);
}
__device__ __forceinline__ void cpa4(unsigned d, const float* s, bool pred) {
    int sz = pred ? 4 : 0;
    asm volatile("cp.async.ca.shared.global [%0],[%1],4,%2;\n"
                 :: "r"(d), "l"(s), "r"(sz));
}
__device__ __forceinline__ void cpa16(unsigned d, const float* s) {
    asm volatile("cp.async.cg.shared.global [%0],[%1],16;\n" :: "r"(d), "l"(s));
}
__device__ __forceinline__ void cp_commit() {
    asm volatile("cp.async.commit_group;\n" ::);
}

// ---------------- tf32 mma.sync ----------------
__device__ __forceinline__ void mma_tf32(float* d,
                                         float a0, float a1, float a2, float a3,
                                         float b0, float b1) {
    asm volatile(
        "mma.sync.aligned.m16n8k8.row.col.f32.tf32.tf32.f32 "
        "{%0,%1,%2,%3},{%4,%5,%6,%7},{%8,%9},{%0,%1,%2,%3};"
        : "+f"(d[0]), "+f"(d[1]), "+f"(d[2]), "+f"(d[3])
        : "r"(__float_as_uint(a0)), "r"(__float_as_uint(a1)),
          "r"(__float_as_uint(a2)), "r"(__float_as_uint(a3)),
          "r"(__float_as_uint(b0)), "r"(__float_as_uint(b1)));
}

// ================= kernel 1: h = relu(hyper @ W1 + b1) =================
__global__ void k_mlp1(const float* __restrict__ hyper,
                       const float* __restrict__ W1,
                       const float* __restrict__ b1)
{
    __shared__ float hy[BATCH * HYP];
    int tid = threadIdx.x;
    for (int i = tid; i < BATCH * HYP; i += 256) hy[i] = hyper[i];
    __syncthreads();

    int g = blockIdx.y;
    int d = blockIdx.x * 256 + tid;
    if (d >= HD) return;

    float acc[BATCH];
    #pragma unroll
    for (int b = 0; b < BATCH; ++b) acc[b] = 0.f;

    const float* w = W1 + (size_t)g * HYP * HD + d;
    #pragma unroll 16
    for (int i = 0; i < HYP; ++i) {
        float wv = w[(size_t)i * HD];
        #pragma unroll
        for (int b = 0; b < BATCH; ++b) acc[b] += hy[b * HYP + i] * wv;
    }
    float bv = b1[g * HD + d];
    #pragma unroll
    for (int b = 0; b < BATCH; ++b)
        g_h[((size_t)(g * BATCH + b)) * HD + d] = fmaxf(acc[b] + bv, 0.f);
}

// ================= kernel 2: gened = h @ W2 + b2 =================
// grid (37, G) = 148 blocks (one wave), block 256. Streams W2 (1.37 GB) at the
// HBM floor with 8 batched float4 LDGs in flight. Epilogue: weights stored
// row-major [oc][k] (= MLP output order -> coalesced float4 stores),
// pre-rounded to tf32 for the MMA conv.
__global__ void __launch_bounds__(256, 1) k_mlp2(const float* __restrict__ W2,
                                                 const float* __restrict__ b2)
{
    int g  = blockIdx.y;
    int o0 = blockIdx.x * 1024 + threadIdx.x * 4;
    bool active = (o0 < NWB);

    __shared__ __align__(16) float hs[32][8];

    u64 acc2[4][4];                 // [batch-pair][j]
    #pragma unroll
    for (int bp = 0; bp < 4; ++bp)
        #pragma unroll
        for (int j = 0; j < 4; ++j) acc2[bp][j] = 0ull;

    const float* W2g = W2 + (size_t)g * HD * NWB;
    int sdd = threadIdx.x >> 3, sb = threadIdx.x & 7;

    for (int d0 = 0; d0 < 2304; d0 += 32) {
        hs[sdd][sb] = g_h[((size_t)(g * BATCH + sb)) * HD + d0 + sdd];
        __syncthreads();
        if (active) {
            #pragma unroll
            for (int du = 0; du < 32; du += 8) {
                float4 w[8];
                #pragma unroll
                for (int j = 0; j < 8; ++j)
                    w[j] = *(const float4*)(W2g + (size_t)(d0 + du + j) * NWB + o0);
                #pragma unroll
                for (int j = 0; j < 8; ++j) {
                    u64 wp[4];
                    wp[0] = pack2(w[j].x, w[j].x);
                    wp[1] = pack2(w[j].y, w[j].y);
                    wp[2] = pack2(w[j].z, w[j].z);
                    wp[3] = pack2(w[j].w, w[j].w);
                    const u64* hrow = (const u64*)&hs[du + j][0];
                    #pragma unroll
                    for (int bp = 0; bp < 4; ++bp) {
                        u64 hp = hrow[bp];
                        fma2(acc2[bp][0], hp, wp[0]);
                        fma2(acc2[bp][1], hp, wp[1]);
                        fma2(acc2[bp][2], hp, wp[2]);
                        fma2(acc2[bp][3], hp, wp[3]);
                    }
                }
            }
        }
        __syncthreads();
    }
    // tail d in [2304, 2324)
    {
        hs[sdd][sb] = (2304 + sdd < HD)
                      ? g_h[((size_t)(g * BATCH + sb)) * HD + 2304 + sdd] : 0.f;
        __syncthreads();
        if (active) {
            for (int dd = 0; dd < 20; ++dd) {
                float4 wv = *(const float4*)(W2g + (size_t)(2304 + dd) * NWB + o0);
                u64 wp[4];
                wp[0] = pack2(wv.x, wv.x);
                wp[1] = pack2(wv.y, wv.y);
                wp[2] = pack2(wv.z, wv.z);
                wp[3] = pack2(wv.w, wv.w);
                const u64* hrow = (const u64*)&hs[dd][0];
                #pragma unroll
                for (int bp = 0; bp < 4; ++bp) {
                    u64 hp = hrow[bp];
                    #pragma unroll
                    for (int j = 0; j < 4; ++j) fma2(acc2[bp][j], hp, wp[j]);
                }
            }
        }
    }

    if (!active) return;

    float bb[4];
    #pragma unroll
    for (int j = 0; j < 4; ++j) bb[j] = b2[(size_t)g * NWB + o0 + j];

    // o0 is a multiple of 4 and NW%4==0, so a 4-chunk is never mixed w/bias.
    #pragma unroll
    for (int bp = 0; bp < 4; ++bp) {
        float2 v0 = unpack2(acc2[bp][0]);
        float2 v1 = unpack2(acc2[bp][1]);
        float2 v2 = unpack2(acc2[bp][2]);
        float2 v3 = unpack2(acc2[bp][3]);
        size_t gb0 = (size_t)(g * BATCH + 2 * bp);
        size_t gb1 = gb0 + 1;
        if (o0 < NW) {
            float4 wa = make_float4(to_tf32(v0.x + bb[0]), to_tf32(v1.x + bb[1]),
                                    to_tf32(v2.x + bb[2]), to_tf32(v3.x + bb[3]));
            float4 wb = make_float4(to_tf32(v0.y + bb[0]), to_tf32(v1.y + bb[1]),
                                    to_tf32(v2.y + bb[2]), to_tf32(v3.y + bb[3]));
            *(float4*)&g_wA[gb0 * NW + o0] = wa;
            *(float4*)&g_wA[gb1 * NW + o0] = wb;
        } else {
            int ob = o0 - NW;
            g_bias[gb0 * NB + ob + 0] = v0.x + bb[0];
            g_bias[gb0 * NB + ob + 1] = v1.x + bb[1];
            g_bias[gb0 * NB + ob + 2] = v2.x + bb[2];
            g_bias[gb0 * NB + ob + 3] = v3.x + bb[3];
            g_bias[gb1 * NB + ob + 0] = v0.y + bb[0];
            g_bias[gb1 * NB + ob + 1] = v1.y + bb[1];
            g_bias[gb1 * NB + ob + 2] = v2.y + bb[2];
            g_bias[gb1 * NB + ob + 3] = v3.y + bb[3];
        }
    }
}

// ================= kernel 3: conv as implicit GEMM on tensor cores =========
// Per (b,g): out[64oc x 4096px] = W[64x576] @ patch[576x4096], tf32 mma.sync.
// Block = (b, g, 2 image rows = 128 px). 8 warps: warpM = wid&3 (16 oc each),
// yy = wid>>2 (which image row; warp covers its full 64-px row -> 8 n-subtiles).
// K streamed in 8-channel slabs (72 k): A slab 64x72 (stride 76, conflict-free),
// image slab 8ch x 4 halo rows x 66 cols, double-buffered via cp.async.
// B fragments gathered directly from the haloed image tile (no im2col matrix).
__global__ void __launch_bounds__(256, 2) k_conv(const float* __restrict__ image,
                                                 float* __restrict__ out)
{
    __shared__ __align__(16) float As[64][76];       // 19456 B
    __shared__ __align__(16) float Xs[2][32][66];    // 2 x 8448 B

    int b = blockIdx.z, g = blockIdx.y, t = blockIdx.x;
    int r0 = t * 2;                                  // image row base

    int tid  = threadIdx.x;
    int wid  = tid >> 5, lane = tid & 31;
    int gid  = lane >> 2, tig = lane & 3;
    int m0   = (wid & 3) * 16;                       // warp's oc base
    int yy   = wid >> 2;                             // 0/1: image row within pair

    const float* wA  = g_wA + (size_t)(g * BATCH + b) * NW;
    const float* img = image + ((size_t)b * CH + g * GC) * HW;

    float acc[8][4];
    #pragma unroll
    for (int ns = 0; ns < 8; ++ns)
        #pragma unroll
        for (int j = 0; j < 4; ++j) acc[ns][j] = 0.f;

    // stage image slab s (channels 8s..8s+7) into buffer buf
    auto stage_img = [&](int s, int buf) {
        for (int i = tid; i < 2112; i += 256) {       // 8ch * 4rows * 66cols
            int cl  = i / 264;
            int rem = i - cl * 264;
            int rr  = rem / 66;
            int cc  = rem - rr * 66;
            int gr  = r0 - 1 + rr;
            int gx  = cc - 1;
            bool ok = (gr >= 0 && gr < 64 && gx >= 0 && gx < 64);
            const float* src = ok ? (img + ((size_t)(s * 8 + cl)) * HW + gr * 64 + gx)
                                  : img;
            cpa4(scvt(&Xs[buf][cl * 4 + rr][cc]), src, ok);
        }
    };
    // stage A slab s: As[oc][0..71] = wA[oc][72s .. 72s+71]
    auto stage_A = [&](int s) {
        for (int i = tid; i < 1152; i += 256) {       // 64 rows * 18 float4
            int oc = i / 18, j = (i - oc * 18) * 4;
            cpa16(scvt(&As[oc][j]), wA + (size_t)oc * 576 + s * 72 + j);
        }
    };

    stage_img(0, 0);
    cp_commit();                                      // group: img0

    for (int s = 0; s < 8; ++s) {
        __syncthreads();                               // A buffer free
        stage_A(s);
        cp_commit();                                   // group: A_s
        if (s + 1 < 8) {
            stage_img(s + 1, (s + 1) & 1);
            cp_commit();                               // group: img_{s+1}
            asm volatile("cp.async.wait_group 1;\n" ::); // A_s + img_s done
        } else {
            asm volatile("cp.async.wait_group 0;\n" ::);
        }
        __syncthreads();

        const float (*X)[66] = Xs[s & 1];

        #pragma unroll
        for (int ks = 0; ks < 9; ++ks) {
            int ka = ks * 8 + tig;
            float a0 = As[m0 + gid][ka];
            float a1 = As[m0 + gid + 8][ka];
            float a2 = As[m0 + gid][ka + 4];
            float a3 = As[m0 + gid + 8][ka + 4];

            // lane's two B k-rows: k = ka and ka+4; decode (c,kh,kw)
            int k0 = ka,      cl0 = k0 / 9, t0 = k0 - cl0 * 9;
            int kh0 = t0 / 3, kw0 = t0 - kh0 * 3;
            int k1 = ka + 4,  cl1 = k1 / 9, t1 = k1 - cl1 * 9;
            int kh1 = t1 / 3, kw1 = t1 - kh1 * 3;
            const float* bp0 = &X[cl0 * 4 + yy + kh0][gid + kw0];
            const float* bp1 = &X[cl1 * 4 + yy + kh1][gid + kw1];

            #pragma unroll
            for (int ns = 0; ns < 8; ++ns)
                mma_tf32(acc[ns], a0, a1, a2, a3, bp0[ns * 8], bp1[ns * 8]);
        }
    }

    // epilogue: bias + store. c-frag: rows gid / gid+8, cols tig*2 / tig*2+1.
    const float* bias = g_bias + (size_t)(g * BATCH + b) * NB;
    float bv0 = bias[m0 + gid];
    float bv1 = bias[m0 + gid + 8];
    float* ob = out + ((size_t)b * CH + g * GC + m0 + gid) * HW + (r0 + yy) * 64;
    #pragma unroll
    for (int ns = 0; ns < 8; ++ns) {
        int x = ns * 8 + tig * 2;
        float2* o0 = (float2*)(ob + x);
        float2* o1 = (float2*)(ob + 8 * HW + x);
        *o0 = make_float2(acc[ns][0] + bv0, acc[ns][1] + bv0);
        *o1 = make_float2(acc[ns][2] + bv1, acc[ns][3] + bv1);
    }
}

// ================= launch =================
extern "C" void kernel_launch(void* const* d_in, const int* in_sizes, int n_in,
                              void* d_out, int out_size)
{
    const float* image = (const float*)d_in[0];
    const float* hyper = (const float*)d_in[1];
    const float* W1    = (const float*)d_in[2];
    const float* b1    = (const float*)d_in[3];
    const float* W2    = (const float*)d_in[4];
    const float* b2    = (const float*)d_in[5];
    float*       out   = (float*)d_out;

    dim3 g1((HD + 255) / 256, G);
    k_mlp1<<<g1, 256>>>(hyper, W1, b1);

    dim3 g2((NWB + 1023) / 1024, G);    // 148 blocks, one wave
    k_mlp2<<<g2, 256>>>(W2, b2);

    dim3 g3(32, G, BATCH);              // 32 row-pair tiles x 4 g x 8 b
    k_conv<<<g3, 256>>>(image, out);
}